// round 16
// baseline (speedup 1.0000x reference)
#include <cuda_runtime.h>
#include <math.h>

#define SEQ  1024
#define NF   256
#define H    1024
#define G4   4096
#define OUTN 1024
#define NB   128
#define JPB  8
#define NTHR 512
#define NLINES 8
#define PERLINE (NB / NLINES)

typedef unsigned long long u64;

__device__ float    g_gx[(size_t)SEQ * G4];
__device__ float    g_h[(size_t)(SEQ + 1) * H];     // row 0 = BSS zeros, never written
__device__ float    g_logits[(size_t)SEQ * OUTN];
__device__ float    g_lse[SEQ];
__device__ u64      g_sorted[(size_t)SEQ * OUTN];
__device__ unsigned g_done[(size_t)(SEQ + 1) * NLINES * 32];

__device__ __forceinline__ float sigm(float x) { return 1.0f / (1.0f + __expf(-x)); }

__device__ __forceinline__ unsigned ld_rlx(const unsigned* p) {
    unsigned v;
    asm volatile("ld.relaxed.gpu.global.u32 %0, [%1];" : "=r"(v) : "l"(p) : "memory");
    return v;
}
__device__ __forceinline__ unsigned ld_acq(const unsigned* p) {
    unsigned v;
    asm volatile("ld.acquire.gpu.global.u32 %0, [%1];" : "=r"(v) : "l"(p) : "memory");
    return v;
}
__device__ __forceinline__ void red_rel(unsigned* p) {
    asm volatile("red.release.gpu.global.add.u32 [%0], 1;" :: "l"(p) : "memory");
}
__device__ __forceinline__ unsigned* done_ctr(int step, int line) {
    return &g_done[((size_t)step * NLINES + line) * 32];
}
__device__ __forceinline__ float dot4(float4 a, float4 b) {
    return a.x * b.x + a.y * b.y + a.z * b.z + a.w * b.w;
}
__device__ __forceinline__ float4 ldg4(const float* p) {
    float4 v;
    asm volatile("ld.global.v4.f32 {%0,%1,%2,%3}, [%4];"
                 : "=f"(v.x), "=f"(v.y), "=f"(v.z), "=f"(v.w) : "l"(p));
    return v;
}

// ---------------- Kernel A ----------------
__global__ void precompute_gx(const float* __restrict__ X,
                              const float* __restrict__ Wih,
                              const float* __restrict__ bih,
                              const float* __restrict__ bhh) {
    __shared__ float Xs[32 * NF];
    const int r  = blockIdx.x * 256 + threadIdx.x;
    const int t0 = blockIdx.y * 32;

    for (int i = threadIdx.x; i < 32 * NF; i += 256)
        Xs[i] = X[(size_t)t0 * NF + i];
    __syncthreads();

    const float bias = bih[r] + bhh[r];
    float acc[32];
#pragma unroll
    for (int tt = 0; tt < 32; tt++) acc[tt] = bias;

    const float4* Wr = (const float4*)(Wih + (size_t)r * NF);
    for (int k4 = 0; k4 < NF / 4; k4++) {
        float4 wv = Wr[k4];
#pragma unroll
        for (int tt = 0; tt < 32; tt++)
            acc[tt] += dot4(wv, *(const float4*)&Xs[tt * NF + k4 * 4]);
    }
#pragma unroll
    for (int tt = 0; tt < 32; tt++)
        g_gx[(size_t)(t0 + tt) * G4 + r] = acc[tt];
}

// ---------------- Kernel B: 2-barrier persistent LSTM ----------------
// Warp w (of 16): jj=w>>1, half=w&1 → all 4 gate rows of j=b*8+jj over its
// 512-col half, weights in 16 float4 regs. h loaded straight to registers.
// Pollers = warp 15 lanes 24..31 (tid 504..511). Activations = tid 0..7.
__global__ void __launch_bounds__(NTHR, 1)
lstm_recurrence(const float* __restrict__ enc,
                const float* __restrict__ Whh,
                const float* __restrict__ Wout,
                const float* __restrict__ bout) {
    __shared__ float4 wout_s[8 * 256];    // 32 KB
    __shared__ float  pbuf[8][2][4];
    __shared__ float  pbuf2[16];

    const int b = blockIdx.x, tid = threadIdx.x;
    const int w = tid >> 5, l = tid & 31;
    const int jj = w >> 1, half = w & 1;
    const int j = b * JPB + jj;
    const int myline = b & (NLINES - 1);

    float4 wh[16];
    const float4* Whh4 = (const float4*)Whh;
#pragma unroll
    for (int g = 0; g < 4; g++)
#pragma unroll
        for (int k = 0; k < 4; k++)
            wh[g * 4 + k] = Whh4[(size_t)(g * H + j) * 256 + half * 128 + k * 32 + l];

    const float4* Wout4 = (const float4*)Wout;
    for (int i = tid; i < 8 * 256; i += NTHR)
        wout_s[i] = Wout4[(size_t)(b * JPB) * 256 + i];

    float c0j = 0.f, boutj = 0.f, gxr0 = 0.f, gxr1 = 0.f, gxr2 = 0.f, gxr3 = 0.f;
    if (tid < JPB) {
        c0j   = enc[(size_t)(SEQ - 1) * H + b * JPB + tid];
        boutj = bout[b * JPB + tid];
        gxr0 = g_gx[0 * H + b * JPB + tid];
        gxr1 = g_gx[1 * H + b * JPB + tid];
        gxr2 = g_gx[2 * H + b * JPB + tid];
        gxr3 = g_gx[3 * H + b * JPB + tid];
    }
    __syncthreads();

    for (int t = 0; t < SEQ; t++) {
        // ---- detect h_t ready (warp-15 pollers; relaxed spin + one acquire) ----
        if (t > 0 && tid >= NTHR - NLINES) {
            const unsigned* c = done_ctr(t, tid - (NTHR - NLINES));
            while (ld_rlx(c) < PERLINE) {}
            ld_acq(c);
        }
        __syncthreads();                                      // bar A

        // ---- load this warp's h half straight to registers ----
        float4 hv0, hv1, hv2, hv3;
        if (t == 0) {
            hv0 = hv1 = hv2 = hv3 = make_float4(0.f, 0.f, 0.f, 0.f);
        } else {
            const float* hp = g_h + (size_t)t * H + half * 512 + l * 4;
            hv0 = ldg4(hp);       hv1 = ldg4(hp + 128);
            hv2 = ldg4(hp + 256); hv3 = ldg4(hp + 384);
        }

        // ---- gate partials ----
        float a0, a1, a2, a3;
        a0 = dot4(wh[0], hv0) + dot4(wh[1], hv1) + dot4(wh[2], hv2) + dot4(wh[3], hv3);
        a1 = dot4(wh[4], hv0) + dot4(wh[5], hv1) + dot4(wh[6], hv2) + dot4(wh[7], hv3);
        a2 = dot4(wh[8], hv0) + dot4(wh[9], hv1) + dot4(wh[10], hv2) + dot4(wh[11], hv3);
        a3 = dot4(wh[12], hv0) + dot4(wh[13], hv1) + dot4(wh[14], hv2) + dot4(wh[15], hv3);
#pragma unroll
        for (int off = 16; off; off >>= 1) {
            a0 += __shfl_down_sync(0xffffffffu, a0, off);
            a1 += __shfl_down_sync(0xffffffffu, a1, off);
            a2 += __shfl_down_sync(0xffffffffu, a2, off);
            a3 += __shfl_down_sync(0xffffffffu, a3, off);
        }
        if (l == 0) {
            pbuf[jj][half][0] = a0; pbuf[jj][half][1] = a1;
            pbuf[jj][half][2] = a2; pbuf[jj][half][3] = a3;
        }

        // ---- Wout partials (h_t → logits[t-1]) ----
        if (t > 0) {
            const float4* ws = &wout_s[jj * 256 + half * 128 + l];
            float s = dot4(ws[0], hv0) + dot4(ws[32], hv1)
                    + dot4(ws[64], hv2) + dot4(ws[96], hv3);
#pragma unroll
            for (int off = 16; off; off >>= 1) s += __shfl_down_sync(0xffffffffu, s, off);
            if (l == 0) pbuf2[jj * 2 + half] = s;
        }
        __syncthreads();                                      // bar C

        // ---- activations + publish + prompt arrive (warp 0, lanes 0..7) ----
        if (tid < JPB) {
            float ig = sigm(pbuf[tid][0][0] + pbuf[tid][1][0] + gxr0);
            float fg = sigm(pbuf[tid][0][1] + pbuf[tid][1][1] + gxr1);
            float gg = tanhf(pbuf[tid][0][2] + pbuf[tid][1][2] + gxr2);
            float og = sigm(pbuf[tid][0][3] + pbuf[tid][1][3] + gxr3);
            float c  = fg * c0j + ig * gg;
            g_h[(size_t)(t + 1) * H + b * JPB + tid] = og * tanhf(c);
            if (t > 0)
                g_logits[(size_t)(t - 1) * OUTN + b * JPB + tid] =
                    pbuf2[tid * 2] + pbuf2[tid * 2 + 1] + boutj;
            __syncwarp(0x000000FFu);          // lanes 0..7 stores done
            if (tid == 0) red_rel(done_ctr(t + 1, myline));   // release covers synced stores
            if (t + 1 < SEQ) {
                gxr0 = g_gx[(size_t)(t + 1) * G4 + 0 * H + b * JPB + tid];
                gxr1 = g_gx[(size_t)(t + 1) * G4 + 1 * H + b * JPB + tid];
                gxr2 = g_gx[(size_t)(t + 1) * G4 + 2 * H + b * JPB + tid];
                gxr3 = g_gx[(size_t)(t + 1) * G4 + 3 * H + b * JPB + tid];
            }
        }
    }

    // ---- epilogue: logits[SEQ-1] = Wout · h_SEQ ----
    if (tid >= NTHR - NLINES) {
        const unsigned* c = done_ctr(SEQ, tid - (NTHR - NLINES));
        while (ld_rlx(c) < PERLINE) {}
        ld_acq(c);
    }
    __syncthreads();
    {
        const float* hp = g_h + (size_t)SEQ * H + half * 512 + l * 4;
        float4 hv0 = ldg4(hp), hv1 = ldg4(hp + 128), hv2 = ldg4(hp + 256), hv3 = ldg4(hp + 384);
        const float4* ws = &wout_s[jj * 256 + half * 128 + l];
        float s = dot4(ws[0], hv0) + dot4(ws[32], hv1) + dot4(ws[64], hv2) + dot4(ws[96], hv3);
#pragma unroll
        for (int off = 16; off; off >>= 1) s += __shfl_down_sync(0xffffffffu, s, off);
        if (l == 0) pbuf2[jj * 2 + half] = s;
    }
    __syncthreads();
    if (tid < JPB)
        g_logits[(size_t)(SEQ - 1) * OUTN + b * JPB + tid] =
            pbuf2[tid * 2] + pbuf2[tid * 2 + 1] + boutj;
}

// ---------------- Kernel C: per-row logsumexp ----------------
__global__ void row_lse() {
    const int t = blockIdx.x, tid = threadIdx.x, w = tid >> 5, l = tid & 31;
    __shared__ float red[8];
    float v[4];
#pragma unroll
    for (int k = 0; k < 4; k++) v[k] = g_logits[(size_t)t * OUTN + tid + k * 256];
    float m = fmaxf(fmaxf(v[0], v[1]), fmaxf(v[2], v[3]));
#pragma unroll
    for (int off = 16; off; off >>= 1) m = fmaxf(m, __shfl_xor_sync(0xffffffffu, m, off));
    if (l == 0) red[w] = m;
    __syncthreads();
    float M = red[0];
#pragma unroll
    for (int i = 1; i < 8; i++) M = fmaxf(M, red[i]);
    float s = 0.f;
#pragma unroll
    for (int k = 0; k < 4; k++) s += expf(v[k] - M);
#pragma unroll
    for (int off = 16; off; off >>= 1) s += __shfl_xor_sync(0xffffffffu, s, off);
    __syncthreads();
    if (l == 0) red[w] = s;
    __syncthreads();
    if (tid == 0) {
        float S = 0.f;
#pragma unroll
        for (int i = 0; i < 8; i++) S += red[i];
        g_lse[t] = M + logf(S);
    }
}

// ---------------- Kernel S: bitonic sort rows ----------------
__global__ void sort_rows() {
    __shared__ u64 key[OUTN];
    const int t = blockIdx.x, tid = threadIdx.x;

    for (int i = tid; i < OUTN; i += 256) {
        unsigned u = __float_as_uint(g_logits[(size_t)t * OUTN + i]);
        unsigned m = (u & 0x80000000u) ? ~u : (u | 0x80000000u);
        key[i] = ((u64)m << 32) | (u64)(OUTN - 1 - i);
    }
    __syncthreads();

    for (int k = 2; k <= OUTN; k <<= 1) {
        for (int jj = k >> 1; jj > 0; jj >>= 1) {
            for (int i = tid; i < OUTN; i += 256) {
                int ix = i ^ jj;
                if (ix > i) {
                    bool descend = (i & k) == 0;
                    u64 a = key[i], c = key[ix];
                    bool sw = descend ? (a < c) : (a > c);
                    if (sw) { key[i] = c; key[ix] = a; }
                }
            }
            __syncthreads();
        }
    }

    for (int i = tid; i < OUTN; i += 256)
        g_sorted[(size_t)t * OUTN + i] = key[i];
}

// ---------------- Kernel D: ballot tour selection ----------------
__global__ void tour_select(float* __restrict__ out, int out_size) {
    __shared__ unsigned vis[32];
    const int l = threadIdx.x;
    vis[l] = 0;
    __syncwarp();

    u64 cur = g_sorted[l];
    float lse_c = g_lse[0];

    for (int t = 0; t < SEQ; t++) {
        u64 nxt = 0; float lse_n = 0.f;
        if (t + 1 < SEQ) {
            nxt   = g_sorted[(size_t)(t + 1) * OUTN + l];
            lse_n = g_lse[t + 1];
        }

        u64 key = cur;
        int batch = 0;
        unsigned ballot;
        for (;;) {
            unsigned idx = OUTN - 1 - (unsigned)(key & 0xFFFFFFFFu);
            bool unvis = ((vis[idx >> 5] >> (idx & 31)) & 1u) == 0u;
            ballot = __ballot_sync(0xffffffffu, unvis);
            if (ballot) break;
            batch++;
            key = g_sorted[(size_t)t * OUTN + batch * 32 + l];
        }
        int wl = __ffs(ballot) - 1;
        u64 wkey = __shfl_sync(0xffffffffu, key, wl);
        unsigned widx = OUTN - 1 - (unsigned)(wkey & 0xFFFFFFFFu);
        if (l == 0) {
            unsigned m = (unsigned)(wkey >> 32);
            unsigned u = (m & 0x80000000u) ? (m ^ 0x80000000u) : ~m;
            float val = __uint_as_float(u);
            if (t < out_size)       out[t] = (float)widx;
            if (SEQ + t < out_size) out[SEQ + t] = val - lse_c;
            vis[widx >> 5] |= 1u << (widx & 31);
        }
        __syncwarp();

        cur = nxt; lse_c = lse_n;
    }
}

// ---------------- launch ----------------
extern "C" void kernel_launch(void* const* d_in, const int* in_sizes, int n_in,
                              void* d_out, int out_size) {
    const float* X    = (const float*)d_in[0];
    const float* enc  = (const float*)d_in[1];
    const float* Wih  = (const float*)d_in[2];
    const float* Whh  = (const float*)d_in[3];
    const float* bih  = (const float*)d_in[4];
    const float* bhh  = (const float*)d_in[5];
    const float* Wout = (const float*)d_in[6];
    const float* bout = (const float*)d_in[7];
    float* out = (float*)d_out;

    void* doneAddr = nullptr; cudaGetSymbolAddress(&doneAddr, g_done);
    cudaMemsetAsync(doneAddr, 0, (size_t)(SEQ + 1) * NLINES * 32 * sizeof(unsigned));

    precompute_gx<<<dim3(16, 32), 256>>>(X, Wih, bih, bhh);
    lstm_recurrence<<<NB, NTHR>>>(enc, Whh, Wout, bout);
    row_lse<<<SEQ, 256>>>();
    sort_rows<<<SEQ, 256>>>();
    tour_select<<<1, 32>>>(out, out_size);
}